// round 3
// baseline (speedup 1.0000x reference)
#include <cuda_runtime.h>

#define FULLM 0xffffffffu
typedef unsigned long long ull;

static __device__ __forceinline__ ull fma2(ull a, ull b, ull c){
    ull d; asm("fma.rn.f32x2 %0, %1, %2, %3;" : "=l"(d) : "l"(a), "l"(b), "l"(c)); return d;
}
static __device__ __forceinline__ ull dup2(float x){
    ull d; asm("mov.b64 %0, {%1, %1};" : "=l"(d) : "f"(x)); return d;
}
static __device__ __forceinline__ float2 unpk(ull a){
    float2 f; asm("mov.b64 {%0, %1}, %2;" : "=f"(f.x), "=f"(f.y) : "l"(a)); return f;
}
static __device__ __forceinline__ float softplus_f(float x){
    return fmaxf(x, 0.f) + __logf(1.f + __expf(-fabsf(x)));
}

constexpr int   BN     = 262144;
constexpr int   GROUPS = BN / 32;          // 8192 block-groups of 32 samples
constexpr int   HPAD   = 276;              // hist row stride (floats), 16B-aligned rows
constexpr float EPSF   = 1e-12f;

__global__ __launch_bounds__(128, 3)
void hist2d_kernel(const float* __restrict__ wi, const float* __restrict__ cond,
                   const float* __restrict__ w0, const float* __restrict__ b0,
                   const float* __restrict__ w1, const float* __restrict__ b1,
                   const float* __restrict__ w2, const float* __restrict__ b2,
                   const float* __restrict__ w3, const float* __restrict__ b3,
                   float* __restrict__ out)
{
    __shared__ __align__(16) float2 s_pair[4][4][32];   // layers 0-2 activations per warp
    __shared__ __align__(16) float2 s_h[16][32];        // h after layer 2, [pair][k]
    __shared__ float s_rows[32][17];                    // unnormalized row sums
    __shared__ __align__(16) float s_hist[32][HPAD];    // unnormalized hist

    const int tid  = threadIdx.x;
    const int lane = tid & 31;
    const int w    = tid >> 5;

    // phase-B tiling: warp = (pairHalf, colHalf); lane owns 4 consecutive cols
    const int colHalf  = w & 1;
    const int pairHalf = (w >> 1) * 8;
    const int c0       = colHalf * 128 + lane * 4;
    const int rowg     = colHalf * 8 + (lane >> 2);
    const float4 b3q   = __ldg((const float4*)(b3 + c0));
    const float* w3c   = w3 + c0;

    for (int g = blockIdx.x; g < GROUPS; g += gridDim.x) {
        const int Sblk = g * 32;

        // ================= Phase A: layers 0-2 for this warp's 8 samples =================
        const int S0 = Sblk + w * 8;
        #pragma unroll
        for (int p2 = 0; p2 < 2; ++p2) {
            if (lane < 20) {
                int pl = p2 * 2 + (lane >= 10);
                int i  = lane % 10;
                int sb = S0 + pl * 2;
                s_pair[w][pl][i] = make_float2(__ldg(&cond[sb*10 + i]), __ldg(&cond[sb*10 + 10 + i]));
            }
        }
        __syncwarp();

        ull acc[4];

        // ---- layer 0: 10 -> 32 ----
        {
            ull b = dup2(__ldg(&b0[lane]));
            #pragma unroll
            for (int p = 0; p < 4; ++p) acc[p] = b;
            #pragma unroll
            for (int k = 0; k < 10; k += 2) {
                ull wkA = dup2(__ldg(&w0[k*32 + lane]));
                ull wkB = dup2(__ldg(&w0[(k+1)*32 + lane]));
                #pragma unroll
                for (int p = 0; p < 4; ++p) {
                    ulonglong2 h2 = *(const ulonglong2*)&s_pair[w][p][k];
                    acc[p] = fma2(h2.x, wkA, acc[p]);
                    acc[p] = fma2(h2.y, wkB, acc[p]);
                }
            }
            __syncwarp();
            #pragma unroll
            for (int p = 0; p < 4; ++p) {
                float2 f = unpk(acc[p]);
                s_pair[w][p][lane] = make_float2(fmaxf(f.x, 0.f), fmaxf(f.y, 0.f));
            }
            __syncwarp();
        }

        // ---- layer 1: 32 -> 32 ----
        {
            ull b = dup2(__ldg(&b1[lane]));
            #pragma unroll
            for (int p = 0; p < 4; ++p) acc[p] = b;
            #pragma unroll 8
            for (int k = 0; k < 32; k += 2) {
                ull wkA = dup2(__ldg(&w1[k*32 + lane]));
                ull wkB = dup2(__ldg(&w1[(k+1)*32 + lane]));
                #pragma unroll
                for (int p = 0; p < 4; ++p) {
                    ulonglong2 h2 = *(const ulonglong2*)&s_pair[w][p][k];
                    acc[p] = fma2(h2.x, wkA, acc[p]);
                    acc[p] = fma2(h2.y, wkB, acc[p]);
                }
            }
            __syncwarp();
            #pragma unroll
            for (int p = 0; p < 4; ++p) {
                float2 f = unpk(acc[p]);
                s_pair[w][p][lane] = make_float2(fmaxf(f.x, 0.f), fmaxf(f.y, 0.f));
            }
            __syncwarp();
        }

        // ---- layer 2: 32 -> 32, publish to block-shared s_h ----
        {
            ull b = dup2(__ldg(&b2[lane]));
            #pragma unroll
            for (int p = 0; p < 4; ++p) acc[p] = b;
            #pragma unroll 8
            for (int k = 0; k < 32; k += 2) {
                ull wkA = dup2(__ldg(&w2[k*32 + lane]));
                ull wkB = dup2(__ldg(&w2[(k+1)*32 + lane]));
                #pragma unroll
                for (int p = 0; p < 4; ++p) {
                    ulonglong2 h2 = *(const ulonglong2*)&s_pair[w][p][k];
                    acc[p] = fma2(h2.x, wkA, acc[p]);
                    acc[p] = fma2(h2.y, wkB, acc[p]);
                }
            }
            __syncwarp();
            #pragma unroll
            for (int p = 0; p < 4; ++p) {
                float2 f = unpk(acc[p]);
                s_h[w*4 + p][lane] = make_float2(fmaxf(f.x, 0.f), fmaxf(f.y, 0.f));
            }
        }
        __syncthreads();

        // ====== Phase B: layer 3, 8 pairs x 4 cols/lane (128 cols/warp) ======
        ull acc3[8][4];
        {
            ull d0 = dup2(b3q.x), d1 = dup2(b3q.y), d2 = dup2(b3q.z), d3 = dup2(b3q.w);
            #pragma unroll
            for (int p = 0; p < 8; ++p) {
                acc3[p][0] = d0; acc3[p][1] = d1; acc3[p][2] = d2; acc3[p][3] = d3;
            }
        }
        #pragma unroll 2
        for (int k = 0; k < 32; k += 2) {
            float4 wA = __ldg((const float4*)(w3c + k*256));
            float4 wB = __ldg((const float4*)(w3c + (k+1)*256));
            ull a0 = dup2(wA.x), a1 = dup2(wA.y), a2 = dup2(wA.z), a3 = dup2(wA.w);
            ull e0 = dup2(wB.x), e1 = dup2(wB.y), e2 = dup2(wB.z), e3 = dup2(wB.w);
            #pragma unroll
            for (int p = 0; p < 8; ++p) {
                ulonglong2 h2 = *(const ulonglong2*)&s_h[pairHalf + p][k];
                acc3[p][0] = fma2(h2.x, a0, acc3[p][0]);
                acc3[p][1] = fma2(h2.x, a1, acc3[p][1]);
                acc3[p][2] = fma2(h2.x, a2, acc3[p][2]);
                acc3[p][3] = fma2(h2.x, a3, acc3[p][3]);
                acc3[p][0] = fma2(h2.y, e0, acc3[p][0]);
                acc3[p][1] = fma2(h2.y, e1, acc3[p][1]);
                acc3[p][2] = fma2(h2.y, e2, acc3[p][2]);
                acc3[p][3] = fma2(h2.y, e3, acc3[p][3]);
            }
        }

        // softplus, hist write (STS.128), register row-sum reduction (4-lane butterflies)
        #pragma unroll
        for (int p = 0; p < 8; ++p) {
            const int P = pairHalf + p;
            float2 f0 = unpk(acc3[p][0]);
            float2 f1 = unpk(acc3[p][1]);
            float2 f2 = unpk(acc3[p][2]);
            float2 f3 = unpk(acc3[p][3]);
            float sa0 = softplus_f(f0.x), sb0 = softplus_f(f0.y);
            float sa1 = softplus_f(f1.x), sb1 = softplus_f(f1.y);
            float sa2 = softplus_f(f2.x), sb2 = softplus_f(f2.y);
            float sa3 = softplus_f(f3.x), sb3 = softplus_f(f3.y);
            *(float4*)&s_hist[2*P    ][c0] = make_float4(sa0, sa1, sa2, sa3);
            *(float4*)&s_hist[2*P + 1][c0] = make_float4(sb0, sb1, sb2, sb3);
            float rx = (sa0 + sa1) + (sa2 + sa3);
            float ry = (sb0 + sb1) + (sb2 + sb3);
            rx += __shfl_xor_sync(FULLM, rx, 1);
            ry += __shfl_xor_sync(FULLM, ry, 1);
            rx += __shfl_xor_sync(FULLM, rx, 2);
            ry += __shfl_xor_sync(FULLM, ry, 2);
            if ((lane & 3) == 0) {
                s_rows[2*P    ][rowg] = rx;
                s_rows[2*P + 1][rowg] = ry;
            }
        }
        __syncthreads();

        // ====== Phase C: inverse-CDF sampling (unnormalized comparisons), 2 samples/warp ======
        const int li = lane & 15;
        #pragma unroll
        for (int j = 0; j < 4; ++j) {
            const int sa   = w * 8 + 2 * j;
            const int samp = (lane < 16) ? sa : (sa + 1);
            const int S    = Sblk + samp;

            float rowsum = s_rows[samp][li];
            float tot = rowsum;
            #pragma unroll
            for (int o = 1; o < 16; o <<= 1) tot += __shfl_xor_sync(FULLM, tot, o);

            float cdf = rowsum;
            #pragma unroll
            for (int d = 1; d < 16; d <<= 1) {
                float t = __shfl_up_sync(FULLM, cdf, d, 16);
                if (li >= d) cdf += t;
            }

            float u_x = __ldg(&wi[S*2]);
            float u_y = __ldg(&wi[S*2 + 1]);
            float uy  = u_y * tot;

            unsigned bal = __ballot_sync(FULLM, cdf < uy);
            unsigned mym = (lane < 16) ? (bal & 0xFFFFu) : (bal >> 16);
            int   iy   = min(__popc(mym), 15);
            float cdfp = __shfl_sync(FULLM, cdf, max(iy - 1, 0), 16);
            cdfp = (iy > 0) ? cdfp : 0.f;
            float py   = __shfl_sync(FULLM, rowsum, iy, 16);
            float yv   = ((float)iy + (uy - cdfp) / fmaxf(py, EPSF)) * 0.0625f;

            float hv   = s_hist[samp][iy*16 + li];       // unnormalized hist row
            float cdfx = hv;
            #pragma unroll
            for (int d = 1; d < 16; d <<= 1) {
                float t = __shfl_up_sync(FULLM, cdfx, d, 16);
                if (li >= d) cdfx += t;
            }
            float ux = u_x * py;
            unsigned balx = __ballot_sync(FULLM, cdfx < ux);
            unsigned mymx = (lane < 16) ? (balx & 0xFFFFu) : (balx >> 16);
            int   ix    = min(__popc(mymx), 15);
            float cdfxp = __shfl_sync(FULLM, cdfx, max(ix - 1, 0), 16);
            cdfxp = (ix > 0) ? cdfxp : 0.f;
            float px    = __shfl_sync(FULLM, hv, ix, 16);
            float xv    = ((float)ix + (ux - cdfxp) / fmaxf(px, EPSF)) * 0.0625f;
            float pout  = (px * 64.f) / tot;

            if (li == 0) {
                out[S*2]       = xv * 2.f - 1.f;
                out[S*2 + 1]   = yv * 2.f - 1.f;
                out[2*BN + S]  = pout;
            }
        }
        __syncthreads();
    }
}

extern "C" void kernel_launch(void* const* d_in, const int* in_sizes, int n_in,
                              void* d_out, int out_size) {
    const float* wi   = (const float*)d_in[0];
    const float* cond = (const float*)d_in[1];
    const float* w0   = (const float*)d_in[2];
    const float* b0   = (const float*)d_in[3];
    const float* w1   = (const float*)d_in[4];
    const float* b1   = (const float*)d_in[5];
    const float* w2   = (const float*)d_in[6];
    const float* b2   = (const float*)d_in[7];
    const float* w3   = (const float*)d_in[8];
    const float* b3   = (const float*)d_in[9];
    (void)in_sizes; (void)n_in; (void)out_size;
    hist2d_kernel<<<2048, 128>>>(wi, cond, w0, b0, w1, b1, w2, b2, w3, b3, (float*)d_out);
}